// round 11
// baseline (speedup 1.0000x reference)
#include <cuda_runtime.h>
#include <math.h>

#define Bdim 1024
#define Ndim 1024
#define Mdim 64
#define EPSV 1e-16f
#define COS_EPS 1e-8f
#define HALF_N 512

// dynamic smem layout (floats)
#define OFF_SAVE 0            // 512 rows x 32 cols = 16384 floats (64 KB)
#define OFF_SC   16384        // 1024 floats: full scores -> wg buffer
#define OFF_W    17408        // 1024 floats: final weights
#define OFF_RA   18432        // 17 floats
#define OFF_RB   18449        // 17 floats
#define SMEM_F   18466
#define SMEM_BYTES (SMEM_F * 4)

#define CLUSTER_SYNC() do { \
    asm volatile("barrier.cluster.arrive.aligned;" ::: "memory"); \
    asm volatile("barrier.cluster.wait.aligned;"   ::: "memory"); } while (0)

__device__ __forceinline__ void st_peer_f32(void* myaddr, unsigned peer, float v) {
    unsigned a = (unsigned)__cvta_generic_to_shared(myaddr);
    unsigned pa;
    asm("mapa.shared::cluster.u32 %0, %1, %2;" : "=r"(pa) : "r"(a), "r"(peer));
    asm volatile("st.shared::cluster.f32 [%0], %1;" :: "r"(pa), "f"(v));
}

// ---------------------------------------------------------------------------
// Block-wide SUM reduction for 512 threads, 2 barriers.
// ---------------------------------------------------------------------------
__device__ __forceinline__ float blk_sum512(float v, float* red, int tid) {
    const int lane = tid & 31, warp = tid >> 5;   // 16 warps
#pragma unroll
    for (int o = 16; o > 0; o >>= 1)
        v += __shfl_xor_sync(0xffffffffu, v, o);
    if (lane == 0) red[warp] = v;
    __syncthreads();
    if (warp == 0) {
        float t = (lane < 16) ? red[lane] : 0.f;
#pragma unroll
        for (int o = 8; o > 0; o >>= 1)
            t += __shfl_xor_sync(0xffffffffu, t, o);
        if (lane == 0) red[16] = t;
    }
    __syncthreads();
    return red[16];
}

// ---------------------------------------------------------------------------
// Fused NTM step, cluster v3: 2-CTA cluster per batch.
// P1 split by rows (512 each, saving own P3 columns to smem);
// P2 redundant full softmax after ONE score exchange + ONE cluster sync;
// P3 split by columns (32 each), own rows from smem, peer rows from L2.
// ---------------------------------------------------------------------------
__global__ void __launch_bounds__(512, 2) __cluster_dims__(2, 1, 1)
fused_ntm(const float* __restrict__ mem,   const float* __restrict__ kk,
          const float* __restrict__ beta,  const float* __restrict__ gg,
          const float* __restrict__ ss,    const float* __restrict__ gamma,
          const float* __restrict__ wprev, const float* __restrict__ ee,
          const float* __restrict__ aa,    float* __restrict__ out) {
    extern __shared__ float smf[];
    float* SAVE = smf + OFF_SAVE;
    float* S_SC = smf + OFF_SC;
    float* S_W  = smf + OFF_W;
    float* REDA = smf + OFF_RA;
    float* REDB = smf + OFF_RB;
    float4* S_R = (float4*)smf;          // overlay on SAVE after P3 loop

    const int b         = blockIdx.x >> 1;
    const unsigned rank = blockIdx.x & 1;
    const unsigned peer = rank ^ 1;
    const int tid  = threadIdx.x;
    const int ml   = tid & 15;           // P1: float4 lane (full row)
    const int rg   = tid >> 4;           // P1: row group 0..31
    const int row0 = rank * HALF_N;

    const float* mb = mem + (size_t)b * Ndim * Mdim;

    // ---- per-b scalars ----
    const float bet = beta[b];
    const float gv  = gg[b];
    const float gm  = gamma[b];
    const float sh0 = ss[b * 3 + 0], sh1 = ss[b * 3 + 1], sh2 = ss[b * 3 + 2];

    // ---- k (+eps) and its norm ----
    float4 k4 = *(const float4*)(kk + b * Mdim + ml * 4);
    const float kx = k4.x + EPSV, ky = k4.y + EPSV;
    const float kz = k4.z + EPSV, kw = k4.w + EPSV;
    float kn = kx * kx + ky * ky + kz * kz + kw * kw;
#pragma unroll
    for (int o = 8; o > 0; o >>= 1) kn += __shfl_xor_sync(0xffffffffu, kn, o);
    const float knorm = fmaxf(sqrtf(kn), COS_EPS);

    // ---- Phase 1: scores for own 512 rows; save own P3 cols to smem ----
    const bool saver = ((ml >> 3) == (int)rank);   // cols in own P3 half
    const int  mlo   = ml - (int)rank * 8;         // 0..7 for savers
#pragma unroll
    for (int grp = 0; grp < 2; grp++) {
        float4 m[8];
#pragma unroll
        for (int j = 0; j < 8; j++) {
            const int n = row0 + grp * 256 + j * 32 + rg;
            m[j] = *(const float4*)(mb + (size_t)n * Mdim + ml * 4);
        }
        if (saver) {
#pragma unroll
            for (int j = 0; j < 8; j++) {
                const int local = grp * 256 + j * 32 + rg;
                *(float4*)(SAVE + local * 32 + mlo * 4) = m[j];
            }
        }
        float v[16];
#pragma unroll
        for (int j = 0; j < 8; j++) {
            const float ax = m[j].x + EPSV, ay = m[j].y + EPSV;
            const float az = m[j].z + EPSV, aw = m[j].w + EPSV;
            float d = ax * kx; d = fmaf(ay, ky, d); d = fmaf(az, kz, d); d = fmaf(aw, kw, d);
            float s = ax * ax; s = fmaf(ay, ay, s); s = fmaf(az, az, s); s = fmaf(aw, aw, s);
            v[j]     = d;
            v[8 + j] = s;
        }
        int cnt = 16;
#pragma unroll
        for (int o = 8; o >= 1; o >>= 1) {
            cnt >>= 1;
            const bool hi = (ml & o);
#pragma unroll
            for (int i = 0; i < cnt; i++) {
                const float send = hi ? v[i] : v[i + cnt];
                const float recv = __shfl_xor_sync(0xffffffffu, send, o);
                v[i] = (hi ? v[i + cnt] : v[i]) + recv;
            }
        }
        const float other = __shfl_xor_sync(0xffffffffu, v[0], 8);
        if (ml < 8)
            S_SC[row0 + grp * 256 + ml * 32 + rg] =
                bet * (v[0] / (fmaxf(sqrtf(other), COS_EPS) * knorm));
    }
    __syncthreads();

    // ---- ship own 512 scores to peer; ONE cluster sync ----
    {
        const float sc = S_SC[row0 + tid];
        st_peer_f32(&S_SC[row0 + tid], peer, sc);
    }
    CLUSTER_SYNC();

    // ---- Phase 2 (redundant, full 1024): softmax -> interp -> shift ->
    //      sharpen -> normalize ----
    {
        const float ex0 = __expf(S_SC[tid]);
        const float ex1 = __expf(S_SC[tid + 512]);
        const float wp0 = __ldg(wprev + b * Ndim + tid);
        const float wp1 = __ldg(wprev + b * Ndim + tid + 512);
        const float esum = blk_sum512(ex0 + ex1, REDA, tid);
        const float inv_e = 1.f / esum;
        const float wg0 = fmaf(gv, ex0 * inv_e - wp0, wp0);
        const float wg1 = fmaf(gv, ex1 * inv_e - wp1, wp1);
        S_SC[tid]       = wg0;          // reuse as wg buffer (reads done pre-reduce)
        S_SC[tid + 512] = wg1;
        __syncthreads();

        const float lo0 = S_SC[(tid + 1023) & 1023];
        const float hi0 = S_SC[(tid + 1)    & 1023];
        const float lo1 = S_SC[(tid + 511)  & 1023];
        const float hi1 = S_SC[(tid + 513)  & 1023];
        const float w0 = __powf(sh0 * lo0 + sh1 * wg0 + sh2 * hi0, gm);
        const float w1 = __powf(sh0 * lo1 + sh1 * wg1 + sh2 * hi1, gm);
        const float wsum = blk_sum512(w0 + w1, REDB, tid);
        const float inv = 1.f / (wsum + EPSV);
        S_W[tid]       = w0 * inv;
        S_W[tid + 512] = w1 * inv;
    }
    __syncthreads();

    // ---- Phase 3: all 1024 rows, own 32 columns ----
    const int ml3 = tid & 7;
    const int rg3 = tid >> 3;                        // 0..63
    const int cb  = (int)rank * 32 + ml3 * 4;

    const float4 e4 = *(const float4*)(ee + b * Mdim + cb);
    const float4 a4 = *(const float4*)(aa + b * Mdim + cb);
    float* ob = out + (size_t)b * (Ndim + 1) * Mdim;

    float rx = 0.f, ry = 0.f, rz = 0.f, rw = 0.f;

    // peer-owned rows from gmem (L2-hot), reverse order, batched 4-deep
#pragma unroll
    for (int half = 1; half >= 0; half--) {
        float4 m[4];
#pragma unroll
        for (int q = 0; q < 4; q++) {
            const int it = (int)peer * 8 + half * 4 + (3 - q);
            const int n = it * 64 + rg3;
            m[q] = __ldcs((const float4*)(mb + (size_t)n * Mdim + cb));
        }
#pragma unroll
        for (int q = 0; q < 4; q++) {
            const int it = (int)peer * 8 + half * 4 + (3 - q);
            const int n = it * 64 + rg3;
            const float wv = S_W[n];
            float4 o4;
            o4.x = fmaf(m[q].x, fmaf(-wv, e4.x, 1.f), wv * a4.x);
            o4.y = fmaf(m[q].y, fmaf(-wv, e4.y, 1.f), wv * a4.y);
            o4.z = fmaf(m[q].z, fmaf(-wv, e4.z, 1.f), wv * a4.z);
            o4.w = fmaf(m[q].w, fmaf(-wv, e4.w, 1.f), wv * a4.w);
            __stcs((float4*)(ob + (size_t)(1 + n) * Mdim + cb), o4);
            rx = fmaf(wv, m[q].x, rx);
            ry = fmaf(wv, m[q].y, ry);
            rz = fmaf(wv, m[q].z, rz);
            rw = fmaf(wv, m[q].w, rw);
        }
    }
    // own rows from smem SAVE
#pragma unroll
    for (int it2 = 0; it2 < 8; it2++) {
        const int it = (int)rank * 8 + it2;
        const int n = it * 64 + rg3;
        const int local = n - row0;
        float4 m4 = *(const float4*)(SAVE + local * 32 + ml3 * 4);
        const float wv = S_W[n];
        float4 o4;
        o4.x = fmaf(m4.x, fmaf(-wv, e4.x, 1.f), wv * a4.x);
        o4.y = fmaf(m4.y, fmaf(-wv, e4.y, 1.f), wv * a4.y);
        o4.z = fmaf(m4.z, fmaf(-wv, e4.z, 1.f), wv * a4.z);
        o4.w = fmaf(m4.w, fmaf(-wv, e4.w, 1.f), wv * a4.w);
        __stcs((float4*)(ob + (size_t)(1 + n) * Mdim + cb), o4);
        rx = fmaf(wv, m4.x, rx);
        ry = fmaf(wv, m4.y, ry);
        rz = fmaf(wv, m4.z, rz);
        rw = fmaf(wv, m4.w, rw);
    }

    // reduce read accumulators (512 -> 8 lanes); overlay on SAVE (done reading)
    __syncthreads();
    S_R[tid] = make_float4(rx, ry, rz, rw);
    __syncthreads();
#pragma unroll
    for (int s = 256; s >= 8; s >>= 1) {
        if (tid < s) {
            float4 x = S_R[tid], y = S_R[tid + s];
            x.x += y.x; x.y += y.y; x.z += y.z; x.w += y.w;
            S_R[tid] = x;
        }
        __syncthreads();
    }
    if (tid < 8)
        __stcs((float4*)(ob + (int)rank * 32 + tid * 4), S_R[tid]);
}

// ---------------------------------------------------------------------------
extern "C" void kernel_launch(void* const* d_in, const int* in_sizes, int n_in,
                              void* d_out, int out_size) {
    const float* mem   = (const float*)d_in[0];
    const float* kk    = (const float*)d_in[1];
    const float* beta  = (const float*)d_in[2];
    const float* gg    = (const float*)d_in[3];
    const float* ss    = (const float*)d_in[4];
    const float* gamma = (const float*)d_in[5];
    const float* wprev = (const float*)d_in[6];
    const float* ee    = (const float*)d_in[7];
    const float* aa    = (const float*)d_in[8];
    float* out = (float*)d_out;

    cudaFuncSetAttribute(fused_ntm,
                         cudaFuncAttributeMaxDynamicSharedMemorySize, SMEM_BYTES);
    fused_ntm<<<2 * Bdim, 512, SMEM_BYTES>>>(mem, kk, beta, gg, ss, gamma,
                                             wprev, ee, aa, out);
}

// round 12
// speedup vs baseline: 1.1485x; 1.1485x over previous
#include <cuda_runtime.h>
#include <math.h>

#define Bdim 1024
#define Ndim 1024
#define Mdim 64
#define EPSV 1e-16f
#define COS_EPS 1e-8f

// dynamic smem layout (float4 units for SAVE, floats elsewhere)
#define OFF_SAVE 0                    // 256 rows x 16 float4 = 4096 float4 (64 KB)
#define OFF_SC   (4096 * 4)           // floats: 1024 scores
#define OFF_WG   (OFF_SC + 1024)      // 1024 interpolated weights
#define OFF_W    (OFF_WG + 1024)      // 1024 final weights
#define OFF_WP   (OFF_W  + 1024)      // 1024 prefetched wprev
#define OFF_RA   (OFF_WP + 1024)      // 17
#define OFF_RB   (OFF_RA + 17)        // 17
#define OFF_SR   (OFF_RB + 17 + 2)    // 512 float4 (8 KB), 16B-align pad
#define SMEM_F   (OFF_SR + 512 * 4)
#define SMEM_BYTES (SMEM_F * 4)

// ---------------------------------------------------------------------------
// cp.async helper
// ---------------------------------------------------------------------------
__device__ __forceinline__ void cp_async8(void* smem_dst, const void* gsrc) {
    unsigned s = (unsigned)__cvta_generic_to_shared(smem_dst);
    asm volatile("cp.async.ca.shared.global [%0], [%1], 8;" :: "r"(s), "l"(gsrc));
}
#define CP_COMMIT() asm volatile("cp.async.commit_group;")
#define CP_WAIT(N)  asm volatile("cp.async.wait_group %0;" :: "n"(N))

// ---------------------------------------------------------------------------
// Block-wide SUM reduction for 512 threads, 2 barriers.
// ---------------------------------------------------------------------------
__device__ __forceinline__ float blk_sum512(float v, float* red, int tid) {
    const int lane = tid & 31, warp = tid >> 5;   // 16 warps
#pragma unroll
    for (int o = 16; o > 0; o >>= 1)
        v += __shfl_xor_sync(0xffffffffu, v, o);
    if (lane == 0) red[warp] = v;
    __syncthreads();
    if (warp == 0) {
        float t = (lane < 16) ? red[lane] : 0.f;
#pragma unroll
        for (int o = 8; o > 0; o >>= 1)
            t += __shfl_xor_sync(0xffffffffu, t, o);
        if (lane == 0) red[16] = t;
    }
    __syncthreads();
    return red[16];
}

// ---------------------------------------------------------------------------
// Fused NTM step: one block per batch b, 512 threads, 2 blocks/SM.
// Grp-0 rows (longest P3 reuse distance) checkpointed to smem in P1.
// ---------------------------------------------------------------------------
__global__ void __launch_bounds__(512, 2) fused_ntm(
        const float* __restrict__ mem,   const float* __restrict__ kk,
        const float* __restrict__ beta,  const float* __restrict__ gg,
        const float* __restrict__ ss,    const float* __restrict__ gamma,
        const float* __restrict__ wprev, const float* __restrict__ ee,
        const float* __restrict__ aa,    float* __restrict__ out) {
    extern __shared__ float smf[];
    float4* SAVE = (float4*)(smf + OFF_SAVE);
    float*  s_sc = smf + OFF_SC;
    float*  s_wg = smf + OFF_WG;
    float*  s_w  = smf + OFF_W;
    float*  s_wp = smf + OFF_WP;
    float*  redA = smf + OFF_RA;
    float*  redB = smf + OFF_RB;
    float4* s_r  = (float4*)(smf + OFF_SR);

    const int b   = blockIdx.x;
    const int tid = threadIdx.x;
    const int ml  = tid & 15;           // float4 lane within a row
    const int rg  = tid >> 4;           // row group 0..31

    const float* mb = mem + (size_t)b * Ndim * Mdim;

    // prefetch wprev row into smem
    cp_async8(&s_wp[tid * 2], wprev + b * Ndim + tid * 2);
    CP_COMMIT();

    // ---- hoist per-b scalars & small vectors ----
    const float bet = beta[b];
    const float gv  = gg[b];
    const float gm  = gamma[b];
    const float sh0 = ss[b * 3 + 0], sh1 = ss[b * 3 + 1], sh2 = ss[b * 3 + 2];
    const float4 e4 = *(const float4*)(ee + b * Mdim + ml * 4);
    const float4 a4 = *(const float4*)(aa + b * Mdim + ml * 4);

    // ---- k (+eps) and its norm (reduced within each 16-lane group) ----
    float4 k4 = *(const float4*)(kk + b * Mdim + ml * 4);
    const float kx = k4.x + EPSV, ky = k4.y + EPSV;
    const float kz = k4.z + EPSV, kw = k4.w + EPSV;
    float kn = kx * kx + ky * ky + kz * kz + kw * kw;
#pragma unroll
    for (int o = 8; o > 0; o >>= 1) kn += __shfl_xor_sync(0xffffffffu, kn, o);
    const float knorm = fmaxf(sqrtf(kn), COS_EPS);

    // ---- Phase 1: scores. 4 groups x 8 front-batched LDG.128, butterfly
    //      reduce-scatter; grp 0 checkpointed to smem for P3 ----
#pragma unroll
    for (int grp = 0; grp < 4; grp++) {
        float4 m[8];
#pragma unroll
        for (int j = 0; j < 8; j++) {
            const int n = grp * 256 + j * 32 + rg;
            m[j] = *(const float4*)(mb + (size_t)n * Mdim + ml * 4);
        }
        if (grp == 0) {
#pragma unroll
            for (int j = 0; j < 8; j++)
                SAVE[(j * 32 + rg) * 16 + ml] = m[j];
        }
        float v[16];
#pragma unroll
        for (int j = 0; j < 8; j++) {
            const float ax = m[j].x + EPSV, ay = m[j].y + EPSV;
            const float az = m[j].z + EPSV, aw = m[j].w + EPSV;
            float d = ax * kx; d = fmaf(ay, ky, d); d = fmaf(az, kz, d); d = fmaf(aw, kw, d);
            float s = ax * ax; s = fmaf(ay, ay, s); s = fmaf(az, az, s); s = fmaf(aw, aw, s);
            v[j]     = d;      // lane j      gets dot of row j
            v[8 + j] = s;      // lane 8 + j  gets ssq of row j
        }
        int cnt = 16;
#pragma unroll
        for (int o = 8; o >= 1; o >>= 1) {
            cnt >>= 1;
            const bool hi = (ml & o);
#pragma unroll
            for (int i = 0; i < cnt; i++) {
                const float send = hi ? v[i] : v[i + cnt];
                const float recv = __shfl_xor_sync(0xffffffffu, send, o);
                v[i] = (hi ? v[i + cnt] : v[i]) + recv;
            }
        }
        const float other = __shfl_xor_sync(0xffffffffu, v[0], 8);
        if (ml < 8) {
            const int n = grp * 256 + ml * 32 + rg;
            s_sc[n] = bet * (v[0] / (fmaxf(sqrtf(other), COS_EPS) * knorm));
        }
    }
    __syncthreads();

    // ---- Phase 2: softmax (no max: |score| <= ~1) / interpolate / shift /
    //      sharpen. 2 n per thread. ----
    {
        const int n0 = tid, n1 = tid + 512;
        const float ex0 = __expf(s_sc[n0]);
        const float ex1 = __expf(s_sc[n1]);
        const float esum = blk_sum512(ex0 + ex1, redA, tid);
        const float inv_esum = 1.f / esum;

        CP_WAIT(0);                         // wprev prefetch complete
        const float wp0 = s_wp[n0];
        const float wp1 = s_wp[n1];
        const float wg0 = fmaf(gv, ex0 * inv_esum - wp0, wp0);
        const float wg1 = fmaf(gv, ex1 * inv_esum - wp1, wp1);
        s_wg[n0] = wg0;
        s_wg[n1] = wg1;
        __syncthreads();

        const float wh0 = sh0 * s_wg[(n0 + Ndim - 1) & (Ndim - 1)]
                        + sh1 * wg0 + sh2 * s_wg[(n0 + 1) & (Ndim - 1)];
        const float wh1 = sh0 * s_wg[(n1 + Ndim - 1) & (Ndim - 1)]
                        + sh1 * wg1 + sh2 * s_wg[(n1 + 1) & (Ndim - 1)];
        const float w0 = __powf(wh0, gm);
        const float w1 = __powf(wh1, gm);
        const float wsum = blk_sum512(w0 + w1, redB, tid);
        const float inv = 1.f / (wsum + EPSV);
        s_w[n0] = w0 * inv;
        s_w[n1] = w1 * inv;
    }
    __syncthreads();

    // ---- Phase 3: read vector + erase/add write.
    //      grps 3..1 from gmem (reverse order, L2-hot); grp 0 from smem ----
    float* ob = out + (size_t)b * (Ndim + 1) * Mdim;

    float rx = 0.f, ry = 0.f, rz = 0.f, rw = 0.f;
#pragma unroll
    for (int grp = 3; grp >= 1; grp--) {
        float4 m[8];
#pragma unroll
        for (int j = 0; j < 8; j++) {
            const int n = grp * 256 + j * 32 + rg;
            m[j] = __ldcs((const float4*)(mb + (size_t)n * Mdim + ml * 4));
        }
#pragma unroll
        for (int j = 0; j < 8; j++) {
            const int n = grp * 256 + j * 32 + rg;
            const float wv = s_w[n];
            float4 o4;
            o4.x = fmaf(m[j].x, fmaf(-wv, e4.x, 1.f), wv * a4.x);
            o4.y = fmaf(m[j].y, fmaf(-wv, e4.y, 1.f), wv * a4.y);
            o4.z = fmaf(m[j].z, fmaf(-wv, e4.z, 1.f), wv * a4.z);
            o4.w = fmaf(m[j].w, fmaf(-wv, e4.w, 1.f), wv * a4.w);
            __stcs((float4*)(ob + (size_t)(1 + n) * Mdim + ml * 4), o4);
            rx = fmaf(wv, m[j].x, rx);
            ry = fmaf(wv, m[j].y, ry);
            rz = fmaf(wv, m[j].z, rz);
            rw = fmaf(wv, m[j].w, rw);
        }
    }
    // grp 0 rows from the smem checkpoint (same thread wrote them in P1)
#pragma unroll
    for (int j = 0; j < 8; j++) {
        const int n = j * 32 + rg;
        float4 m4 = SAVE[(j * 32 + rg) * 16 + ml];
        const float wv = s_w[n];
        float4 o4;
        o4.x = fmaf(m4.x, fmaf(-wv, e4.x, 1.f), wv * a4.x);
        o4.y = fmaf(m4.y, fmaf(-wv, e4.y, 1.f), wv * a4.y);
        o4.z = fmaf(m4.z, fmaf(-wv, e4.z, 1.f), wv * a4.z);
        o4.w = fmaf(m4.w, fmaf(-wv, e4.w, 1.f), wv * a4.w);
        __stcs((float4*)(ob + (size_t)(1 + n) * Mdim + ml * 4), o4);
        rx = fmaf(wv, m4.x, rx);
        ry = fmaf(wv, m4.y, ry);
        rz = fmaf(wv, m4.z, rz);
        rw = fmaf(wv, m4.w, rw);
    }

    // reduce read accumulators (512 -> 16 lanes of ml)
    s_r[tid] = make_float4(rx, ry, rz, rw);
    __syncthreads();
#pragma unroll
    for (int s = 256; s >= 16; s >>= 1) {
        if (tid < s) {
            float4 x = s_r[tid], y = s_r[tid + s];
            x.x += y.x; x.y += y.y; x.z += y.z; x.w += y.w;
            s_r[tid] = x;
        }
        __syncthreads();
    }
    if (tid < 16) __stcs((float4*)(ob + tid * 4), s_r[tid]);   // read row
}

// ---------------------------------------------------------------------------
extern "C" void kernel_launch(void* const* d_in, const int* in_sizes, int n_in,
                              void* d_out, int out_size) {
    const float* mem   = (const float*)d_in[0];
    const float* kk    = (const float*)d_in[1];
    const float* beta  = (const float*)d_in[2];
    const float* gg    = (const float*)d_in[3];
    const float* ss    = (const float*)d_in[4];
    const float* gamma = (const float*)d_in[5];
    const float* wprev = (const float*)d_in[6];
    const float* ee    = (const float*)d_in[7];
    const float* aa    = (const float*)d_in[8];
    float* out = (float*)d_out;

    cudaFuncSetAttribute(fused_ntm,
                         cudaFuncAttributeMaxDynamicSharedMemorySize, SMEM_BYTES);
    fused_ntm<<<Bdim, 512, SMEM_BYTES>>>(mem, kk, beta, gg, ss, gamma,
                                         wprev, ee, aa, out);
}